// round 11
// baseline (speedup 1.0000x reference)
#include <cuda_runtime.h>
#include <cstdint>

// H100SmartEmbedding: out[r, :] = concat(price[0], size[0], exch[r%3], pair[r%7],
//                                        level[r%15], time[r%31]), 6 x 128 fp32.
//
// Period trick: lcm(3,7,15,31) = 3255. Work in 4-ROW GROUPS: group g ≡ residue
// (mod 3255) -> rows 4g..4g+3 have block-constant residues mod 3/7/15/31, so a
// block's ENTIRE output content is one repeated 12KB tile.
//
// R11 probe: route the write stream through the TMA/bulk-async engine instead
// of per-thread STG. Stage the 12KB tile in SMEM once, fence.proxy.async, then
// one elected thread fires one cp.async.bulk (12KB) per destination group —
// fire-and-forget, no per-wavefront LSU overhead. DRAM-ceiling model predicts
// neutral (~58us); if the STG path was paying L1tex wavefront overhead, this
// exposes it (upside 55-57us).

#define PERIOD 3255
#define SPLITG 2          // splits per residue class (over groups) -> grid 6510
#define GROUP  4          // rows per bulk store
#define GROUP_BYTES (GROUP * 768 * 4)   // 12288

__device__ __forceinline__ uint32_t smem_u32(const void* p) {
    uint32_t a;
    asm("{ .reg .u64 t; cvta.to.shared.u64 t, %1; cvt.u32.u64 %0, t; }"
        : "=r"(a) : "l"(p));
    return a;
}

__global__ void __launch_bounds__(256)
smart_embedding_tma(const float4* __restrict__ price,
                    const float4* __restrict__ size_,
                    const float4* __restrict__ exch,
                    const float4* __restrict__ pair,
                    const float4* __restrict__ level,
                    const float4* __restrict__ timew,
                    float* __restrict__ out,
                    int num_features)
{
    __shared__ alignas(128) float4 buf[GROUP * 192];   // 12KB tile

    const int residue = blockIdx.x;   // group residue, 0..PERIOD-1
    const int chunk   = blockIdx.y;   // 0..SPLITG-1

    // Fill the tile: rows 4*residue+i (i=0..3); residues mod 3/7/15/31 are
    // identical for every group this block writes. 768 float4s / 256 threads.
    #pragma unroll
    for (int idx = threadIdx.x; idx < GROUP * 192; idx += 256) {
        const int i   = idx / 192;       // row within group
        const int t   = idx % 192;
        const int sec = t >> 5;          // section 0..5
        const int c4  = t & 31;          // float4 within section
        const int rb  = 4 * residue + i; // representative row

        const float4* src;
        if (sec == 0)      src = price + c4;
        else if (sec == 1) src = size_ + c4;
        else if (sec == 2) src = exch  + (rb % 3)  * 32 + c4;
        else if (sec == 3) src = pair  + (rb % 7)  * 32 + c4;
        else if (sec == 4) src = level + (rb % 15) * 32 + c4;
        else               src = timew + (rb % 31) * 32 + c4;
        buf[idx] = __ldg(src);
    }
    __syncthreads();
    // Make generic-proxy SMEM writes visible to the async (bulk-copy) proxy.
    asm volatile("fence.proxy.async.shared::cta;" ::: "memory");

    // Groups handled: residue + chunk*PERIOD, stepping SPLITG*PERIOD.
    const int num_groups = num_features >> 2;
    if (threadIdx.x == 0) {
        const uint32_t s = smem_u32(buf);
        const uint32_t nbytes = GROUP_BYTES;
        int g = residue + chunk * PERIOD;
        for (; g < num_groups; g += SPLITG * PERIOD) {
            uint64_t dst = (uint64_t)(uintptr_t)out + (uint64_t)g * GROUP_BYTES;
            asm volatile(
                "cp.async.bulk.global.shared::cta.bulk_group [%0], [%1], %2;"
                :: "l"(dst), "r"(s), "r"(nbytes) : "memory");
        }
        asm volatile("cp.async.bulk.commit_group;" ::: "memory");
        asm volatile("cp.async.bulk.wait_group 0;" ::: "memory");
    }
}

// Tail: rows not covered by 4-row groups (num_features % 4; 0 for this dataset).
__global__ void __launch_bounds__(192)
smart_embedding_tail(const float4* __restrict__ price,
                     const float4* __restrict__ size_,
                     const float4* __restrict__ exch,
                     const float4* __restrict__ pair,
                     const float4* __restrict__ level,
                     const float4* __restrict__ timew,
                     float4* __restrict__ out,
                     int row_base)
{
    const int row = row_base + blockIdx.x;
    const int t   = threadIdx.x;
    const int sec = t >> 5;
    const int c4  = t & 31;
    float4 v;
    if (sec == 0)      v = __ldg(&price[c4]);
    else if (sec == 1) v = __ldg(&size_[c4]);
    else if (sec == 2) v = __ldg(&exch[(row % 3) * 32 + c4]);
    else if (sec == 3) v = __ldg(&pair[(row % 7) * 32 + c4]);
    else if (sec == 4) v = __ldg(&level[(row % 15) * 32 + c4]);
    else               v = __ldg(&timew[(row % 31) * 32 + c4]);
    out[(size_t)row * 192 + t] = v;
}

extern "C" void kernel_launch(void* const* d_in, const int* in_sizes, int n_in,
                              void* d_out, int out_size)
{
    const float4* price = (const float4*)d_in[0];
    const float4* size_ = (const float4*)d_in[1];
    const float4* exch  = (const float4*)d_in[2];
    const float4* pair  = (const float4*)d_in[3];
    const float4* level = (const float4*)d_in[4];
    const float4* timew = (const float4*)d_in[5];

    // num_features lives in device memory (d_in[6]); deriving it host-side
    // from out_size keeps kernel_launch graph-capturable.
    const int num_features = out_size / 768;

    dim3 grid(PERIOD, SPLITG, 1);
    smart_embedding_tma<<<grid, 256>>>(price, size_, exch, pair, level, timew,
                                       (float*)d_out, num_features);

    const int rem = num_features & 3;
    if (rem) {
        smart_embedding_tail<<<rem, 192>>>(price, size_, exch, pair, level,
                                           timew, (float4*)d_out,
                                           num_features - rem);
    }
}

// round 12
// speedup vs baseline: 1.0523x; 1.0523x over previous
#include <cuda_runtime.h>
#include <cstdint>

// H100SmartEmbedding: out[r, :] = concat(price[0], size[0], exch[r%3], pair[r%7],
//                                        level[r%15], time[r%31]), 6 x 128 fp32.
//
// Period trick: lcm(3,7,15,31) = 3255. Work in ROW PAIRS: pairs p ≡ residue
// (mod 3255) -> rows 2p,2p+1 have block-constant residues mod 3/7/15/31, so
// each thread loads its 32B table chunk ONCE; mainloop is a pure store stream.
//
// FINAL (= R8, best of 11 rounds, reproduced at 57.82/57.86us):
//   192 thr, each owns one 32B chunk of a 6KB row-pair; STG.256 via
//   st.global.cs.v8.f32; SPLITP=6 (grid 19530, 13.2 waves).
// Verified at the HBM3e pure-write ceiling (~6.0 TB/s, ~75% of spec):
//   - STG.128 / STG.256 / TMA bulk-async all hit the same DRAM rate
//     (write path is LTS/DRAM-bound, front-end independent).
//   - block geometry, split factor, caching hint, unroll, grid shape: neutral.
//   - coarser SPLITP=3 with STG.256 regressed (store depth comes from wave
//     parallelism once instruction count is halved).

#define PERIOD 3255
#define SPLITP 6   // splits per residue class (over pairs) -> grid 19530

__global__ void __launch_bounds__(192)
smart_embedding_kernel(const float4* __restrict__ price,
                       const float4* __restrict__ size_,
                       const float4* __restrict__ exch,
                       const float4* __restrict__ pair,
                       const float4* __restrict__ level,
                       const float4* __restrict__ timew,
                       float* __restrict__ out,
                       int num_features)
{
    const int t   = threadIdx.x;     // 0..191
    const int rip = t / 96;          // row-in-pair: 0 or 1
    const int u   = t % 96;          // chunk within row (96 x 8 floats = 768)
    const int sec = u >> 4;          // section 0..5
    const int c8  = u & 15;          // 32B chunk within the 128-float section

    const int residue = blockIdx.x;  // pair residue, 0..PERIOD-1
    const int chunk   = blockIdx.y;  // 0..SPLITP-1

    // Row this lane serves at pair p: r = 2p + rip, p ≡ residue (mod 3255)
    // -> r ≡ 2*residue + rip (mod 3255): table rows are block-constant.
    const int rbase = 2 * residue + rip;

    // One-time 32B table load per thread (tables: 31.75KB total, L1/L2-hot).
    const float4* src;
    if (sec == 0) {
        src = price + c8 * 2;
    } else if (sec == 1) {
        src = size_ + c8 * 2;
    } else if (sec == 2) {
        src = exch + (rbase % 3) * 32 + c8 * 2;
    } else if (sec == 3) {
        src = pair + (rbase % 7) * 32 + c8 * 2;
    } else if (sec == 4) {
        src = level + (rbase % 15) * 32 + c8 * 2;
    } else {
        src = timew + (rbase % 31) * 32 + c8 * 2;
    }
    const float4 v0 = __ldg(src);
    const float4 v1 = __ldg(src + 1);

    // Pairs handled by this block: residue + chunk*PERIOD, step SPLITP*PERIOD.
    const int num_pairs = num_features >> 1;
    int p = residue + chunk * PERIOD;
    if (p >= num_pairs) return;

    const int    pstride = SPLITP * PERIOD;
    const size_t stepf   = (size_t)pstride * 1536;   // floats per pair-stride
    float* ptr = out + (size_t)p * 1536 + t * 8;

    // Pure 256-bit store stream; .cs = evict-first for write-once data.
    #pragma unroll 4
    for (; p < num_pairs; p += pstride) {
        asm volatile(
            "st.global.cs.v8.f32 [%0], {%1, %2, %3, %4, %5, %6, %7, %8};"
            :: "l"(ptr),
               "f"(v0.x), "f"(v0.y), "f"(v0.z), "f"(v0.w),
               "f"(v1.x), "f"(v1.y), "f"(v1.z), "f"(v1.w)
            : "memory");
        ptr += stepf;
    }
}

// Tail for odd num_features (not hit for this dataset: 131072 is even).
__global__ void __launch_bounds__(192)
smart_embedding_tail(const float4* __restrict__ price,
                     const float4* __restrict__ size_,
                     const float4* __restrict__ exch,
                     const float4* __restrict__ pair,
                     const float4* __restrict__ level,
                     const float4* __restrict__ timew,
                     float4* __restrict__ out,
                     int row)
{
    const int t   = threadIdx.x;
    const int sec = t >> 5;
    const int c4  = t & 31;
    float4 v;
    if (sec == 0)      v = __ldg(&price[c4]);
    else if (sec == 1) v = __ldg(&size_[c4]);
    else if (sec == 2) v = __ldg(&exch[(row % 3) * 32 + c4]);
    else if (sec == 3) v = __ldg(&pair[(row % 7) * 32 + c4]);
    else if (sec == 4) v = __ldg(&level[(row % 15) * 32 + c4]);
    else               v = __ldg(&timew[(row % 31) * 32 + c4]);
    out[(size_t)row * 192 + t] = v;
}

extern "C" void kernel_launch(void* const* d_in, const int* in_sizes, int n_in,
                              void* d_out, int out_size)
{
    const float4* price = (const float4*)d_in[0];
    const float4* size_ = (const float4*)d_in[1];
    const float4* exch  = (const float4*)d_in[2];
    const float4* pair  = (const float4*)d_in[3];
    const float4* level = (const float4*)d_in[4];
    const float4* timew = (const float4*)d_in[5];

    // num_features lives in device memory (d_in[6]); deriving it host-side
    // from out_size keeps kernel_launch graph-capturable.
    const int num_features = out_size / 768;

    dim3 grid(PERIOD, SPLITP, 1);
    smart_embedding_kernel<<<grid, 192>>>(price, size_, exch, pair, level,
                                          timew, (float*)d_out, num_features);
    if (num_features & 1) {
        smart_embedding_tail<<<1, 192>>>(price, size_, exch, pair, level,
                                         timew, (float4*)d_out,
                                         num_features - 1);
    }
}

// round 13
// speedup vs baseline: 1.0529x; 1.0006x over previous
#include <cuda_runtime.h>
#include <cstdint>

// H100SmartEmbedding: out[r, :] = concat(price[0], size[0], exch[r%3], pair[r%7],
//                                        level[r%15], time[r%31]), 6 x 128 fp32.
//
// Period trick: lcm(3,7,15,31) = 3255. Work in ROW PAIRS: pairs p ≡ residue
// (mod 3255) -> rows 2p,2p+1 have block-constant residues mod 3/7/15/31, so
// each thread loads its 32B table chunk ONCE; mainloop is a pure store stream.
//
// R13 probe: SPLITP 6 -> 12 (grid 39060, ~26 waves, ~3.4 pairs/block).
// Wave-granularity is the only axis that ever moved the needle, and both prior
// data points (3: 59.4us, 6: 57.8us) say finer is better for the STG.256
// stream. This completes the bracket; if flat/regressed, SPLITP=6 (R8) final.

#define PERIOD 3255
#define SPLITP 12   // splits per residue class (over pairs) -> grid 39060

__global__ void __launch_bounds__(192)
smart_embedding_kernel(const float4* __restrict__ price,
                       const float4* __restrict__ size_,
                       const float4* __restrict__ exch,
                       const float4* __restrict__ pair,
                       const float4* __restrict__ level,
                       const float4* __restrict__ timew,
                       float* __restrict__ out,
                       int num_features)
{
    const int t   = threadIdx.x;     // 0..191
    const int rip = t / 96;          // row-in-pair: 0 or 1
    const int u   = t % 96;          // chunk within row (96 x 8 floats = 768)
    const int sec = u >> 4;          // section 0..5
    const int c8  = u & 15;          // 32B chunk within the 128-float section

    const int residue = blockIdx.x;  // pair residue, 0..PERIOD-1
    const int chunk   = blockIdx.y;  // 0..SPLITP-1

    // Row this lane serves at pair p: r = 2p + rip, p ≡ residue (mod 3255)
    // -> r ≡ 2*residue + rip (mod 3255): table rows are block-constant.
    const int rbase = 2 * residue + rip;

    // One-time 32B table load per thread (tables: 31.75KB total, L1/L2-hot).
    const float4* src;
    if (sec == 0) {
        src = price + c8 * 2;
    } else if (sec == 1) {
        src = size_ + c8 * 2;
    } else if (sec == 2) {
        src = exch + (rbase % 3) * 32 + c8 * 2;
    } else if (sec == 3) {
        src = pair + (rbase % 7) * 32 + c8 * 2;
    } else if (sec == 4) {
        src = level + (rbase % 15) * 32 + c8 * 2;
    } else {
        src = timew + (rbase % 31) * 32 + c8 * 2;
    }
    const float4 v0 = __ldg(src);
    const float4 v1 = __ldg(src + 1);

    // Pairs handled by this block: residue + chunk*PERIOD, step SPLITP*PERIOD.
    const int num_pairs = num_features >> 1;
    int p = residue + chunk * PERIOD;
    if (p >= num_pairs) return;

    const int    pstride = SPLITP * PERIOD;
    const size_t stepf   = (size_t)pstride * 1536;   // floats per pair-stride
    float* ptr = out + (size_t)p * 1536 + t * 8;

    // Pure 256-bit store stream; .cs = evict-first for write-once data.
    #pragma unroll 4
    for (; p < num_pairs; p += pstride) {
        asm volatile(
            "st.global.cs.v8.f32 [%0], {%1, %2, %3, %4, %5, %6, %7, %8};"
            :: "l"(ptr),
               "f"(v0.x), "f"(v0.y), "f"(v0.z), "f"(v0.w),
               "f"(v1.x), "f"(v1.y), "f"(v1.z), "f"(v1.w)
            : "memory");
        ptr += stepf;
    }
}

// Tail for odd num_features (not hit for this dataset: 131072 is even).
__global__ void __launch_bounds__(192)
smart_embedding_tail(const float4* __restrict__ price,
                     const float4* __restrict__ size_,
                     const float4* __restrict__ exch,
                     const float4* __restrict__ pair,
                     const float4* __restrict__ level,
                     const float4* __restrict__ timew,
                     float4* __restrict__ out,
                     int row)
{
    const int t   = threadIdx.x;
    const int sec = t >> 5;
    const int c4  = t & 31;
    float4 v;
    if (sec == 0)      v = __ldg(&price[c4]);
    else if (sec == 1) v = __ldg(&size_[c4]);
    else if (sec == 2) v = __ldg(&exch[(row % 3) * 32 + c4]);
    else if (sec == 3) v = __ldg(&pair[(row % 7) * 32 + c4]);
    else if (sec == 4) v = __ldg(&level[(row % 15) * 32 + c4]);
    else               v = __ldg(&timew[(row % 31) * 32 + c4]);
    out[(size_t)row * 192 + t] = v;
}

extern "C" void kernel_launch(void* const* d_in, const int* in_sizes, int n_in,
                              void* d_out, int out_size)
{
    const float4* price = (const float4*)d_in[0];
    const float4* size_ = (const float4*)d_in[1];
    const float4* exch  = (const float4*)d_in[2];
    const float4* pair  = (const float4*)d_in[3];
    const float4* level = (const float4*)d_in[4];
    const float4* timew = (const float4*)d_in[5];

    // num_features lives in device memory (d_in[6]); deriving it host-side
    // from out_size keeps kernel_launch graph-capturable.
    const int num_features = out_size / 768;

    dim3 grid(PERIOD, SPLITP, 1);
    smart_embedding_kernel<<<grid, 192>>>(price, size_, exch, pair, level,
                                          timew, (float*)d_out, num_features);
    if (num_features & 1) {
        smart_embedding_tail<<<1, 192>>>(price, size_, exch, pair, level,
                                         timew, (float4*)d_out,
                                         num_features - 1);
    }
}

// round 14
// speedup vs baseline: 1.0576x; 1.0044x over previous
#include <cuda_runtime.h>
#include <cstdint>

// H100SmartEmbedding: out[r, :] = concat(price[0], size[0], exch[r%3], pair[r%7],
//                                        level[r%15], time[r%31]), 6 x 128 fp32.
//
// FINAL KERNEL (R8; best of 13 rounds: 57.82us, reproduced 57.86/58.08/58.11).
//
// Structure: lcm(3,7,15,31) = 3255. Work in ROW PAIRS: pairs p ≡ residue
// (mod 3255) -> rows 2p,2p+1 have block-constant residues mod 3/7/15/31, so
// each thread loads its 32B table chunk ONCE; the mainloop is a pure
// 256-bit store stream (st.global.cs.v8.f32), SPLITP=6 -> grid 19530.
//
// Roofline verdict (measured, 13 rounds): workload is pinned at the HBM3e
// pure-write ceiling, ~6.0 TB/s = ~75% of the 8 TB/s mixed-traffic spec.
//   - STG.128 / STG.256 / TMA bulk-async all hit the same DRAM rate
//     (write path is DRAM-bound, front-end independent).
//   - split bracket {3: 59.4, 6: 57.8, 12: 58.1} -> flat optimum at 6-12.
//   - block shape, caching hint, unroll depth, grid layout: all neutral.
//   - SM-side pipes <31% of any resource throughout.

#define PERIOD 3255
#define SPLITP 6   // splits per residue class (over pairs) -> grid 19530

__global__ void __launch_bounds__(192)
smart_embedding_kernel(const float4* __restrict__ price,
                       const float4* __restrict__ size_,
                       const float4* __restrict__ exch,
                       const float4* __restrict__ pair,
                       const float4* __restrict__ level,
                       const float4* __restrict__ timew,
                       float* __restrict__ out,
                       int num_features)
{
    const int t   = threadIdx.x;     // 0..191
    const int rip = t / 96;          // row-in-pair: 0 or 1
    const int u   = t % 96;          // chunk within row (96 x 8 floats = 768)
    const int sec = u >> 4;          // section 0..5
    const int c8  = u & 15;          // 32B chunk within the 128-float section

    const int residue = blockIdx.x;  // pair residue, 0..PERIOD-1
    const int chunk   = blockIdx.y;  // 0..SPLITP-1

    // Row this lane serves at pair p: r = 2p + rip, p ≡ residue (mod 3255)
    // -> r ≡ 2*residue + rip (mod 3255): table rows are block-constant.
    const int rbase = 2 * residue + rip;

    // One-time 32B table load per thread (tables: 31.75KB total, L1/L2-hot).
    const float4* src;
    if (sec == 0) {
        src = price + c8 * 2;
    } else if (sec == 1) {
        src = size_ + c8 * 2;
    } else if (sec == 2) {
        src = exch + (rbase % 3) * 32 + c8 * 2;
    } else if (sec == 3) {
        src = pair + (rbase % 7) * 32 + c8 * 2;
    } else if (sec == 4) {
        src = level + (rbase % 15) * 32 + c8 * 2;
    } else {
        src = timew + (rbase % 31) * 32 + c8 * 2;
    }
    const float4 v0 = __ldg(src);
    const float4 v1 = __ldg(src + 1);

    // Pairs handled by this block: residue + chunk*PERIOD, step SPLITP*PERIOD.
    const int num_pairs = num_features >> 1;
    int p = residue + chunk * PERIOD;
    if (p >= num_pairs) return;

    const int    pstride = SPLITP * PERIOD;
    const size_t stepf   = (size_t)pstride * 1536;   // floats per pair-stride
    float* ptr = out + (size_t)p * 1536 + t * 8;

    // Pure 256-bit store stream; .cs = evict-first for write-once data.
    #pragma unroll 4
    for (; p < num_pairs; p += pstride) {
        asm volatile(
            "st.global.cs.v8.f32 [%0], {%1, %2, %3, %4, %5, %6, %7, %8};"
            :: "l"(ptr),
               "f"(v0.x), "f"(v0.y), "f"(v0.z), "f"(v0.w),
               "f"(v1.x), "f"(v1.y), "f"(v1.z), "f"(v1.w)
            : "memory");
        ptr += stepf;
    }
}

// Tail for odd num_features (not hit for this dataset: 131072 is even).
__global__ void __launch_bounds__(192)
smart_embedding_tail(const float4* __restrict__ price,
                     const float4* __restrict__ size_,
                     const float4* __restrict__ exch,
                     const float4* __restrict__ pair,
                     const float4* __restrict__ level,
                     const float4* __restrict__ timew,
                     float4* __restrict__ out,
                     int row)
{
    const int t   = threadIdx.x;
    const int sec = t >> 5;
    const int c4  = t & 31;
    float4 v;
    if (sec == 0)      v = __ldg(&price[c4]);
    else if (sec == 1) v = __ldg(&size_[c4]);
    else if (sec == 2) v = __ldg(&exch[(row % 3) * 32 + c4]);
    else if (sec == 3) v = __ldg(&pair[(row % 7) * 32 + c4]);
    else if (sec == 4) v = __ldg(&level[(row % 15) * 32 + c4]);
    else               v = __ldg(&timew[(row % 31) * 32 + c4]);
    out[(size_t)row * 192 + t] = v;
}

extern "C" void kernel_launch(void* const* d_in, const int* in_sizes, int n_in,
                              void* d_out, int out_size)
{
    const float4* price = (const float4*)d_in[0];
    const float4* size_ = (const float4*)d_in[1];
    const float4* exch  = (const float4*)d_in[2];
    const float4* pair  = (const float4*)d_in[3];
    const float4* level = (const float4*)d_in[4];
    const float4* timew = (const float4*)d_in[5];

    // num_features lives in device memory (d_in[6]); deriving it host-side
    // from out_size keeps kernel_launch graph-capturable.
    const int num_features = out_size / 768;

    dim3 grid(PERIOD, SPLITP, 1);
    smart_embedding_kernel<<<grid, 192>>>(price, size_, exch, pair, level,
                                          timew, (float*)d_out, num_features);
    if (num_features & 1) {
        smart_embedding_tail<<<1, 192>>>(price, size_, exch, pair, level,
                                         timew, (float4*)d_out,
                                         num_features - 1);
    }
}